// round 15
// baseline (speedup 1.0000x reference)
#include <cuda_runtime.h>
#include <math.h>

#define NB    4
#define NCH   256
#define FH    38
#define FW    38
#define HW    (FH * FW)            // 1444
#define PH    7
#define PW    7
#define SCALE 0.0625f
#define BINS  (PH * PW)            // 49
#define TOTAL (NCH * BINS)         // 12544
#define CG    128                  // channels per block (lane covers 4 via float4)
#define NCGRP (NCH / CG)           // 2
#define BS    4                    // bin splits (z)
#define LMAX  13                   // max bins per split

// Scratch: feat transposed to (B, H*W, C). float4 => 16B-aligned base.
__device__ float4 g_feat_t4[NB * HW * NCH / 4];

__global__ __launch_bounds__(256) void transpose_kernel(const float* __restrict__ feat)
{
    __shared__ float tile[32][33];
    const int b   = blockIdx.z;
    const int hw0 = blockIdx.x * 32;
    const int c0  = blockIdx.y * 32;
    const int tx  = threadIdx.x;     // 0..31
    const int ty  = threadIdx.y;     // 0..7

    const float* src = feat + b * NCH * HW;
#pragma unroll
    for (int i = 0; i < 4; ++i) {
        int c  = c0 + ty + i * 8;
        int hw = hw0 + tx;
        tile[ty + i * 8][tx] = (hw < HW) ? src[c * HW + hw] : 0.0f;
    }
    __syncthreads();
    float* dst = (float*)g_feat_t4 + b * HW * NCH;
#pragma unroll
    for (int i = 0; i < 4; ++i) {
        int hw = hw0 + ty + i * 8;
        int c  = c0 + tx;
        if (hw < HW) dst[hw * NCH + c] = tile[tx][ty + i * 8];
    }
}

__global__ __launch_bounds__(256) void roipool2_kernel(
    const float* __restrict__ rois,
    const int*   __restrict__ roib,
    float*       __restrict__ out)
{
    const int n    = blockIdx.y;
    const int c0   = blockIdx.x * CG;
    const int z    = blockIdx.z;
    const int b0   = (z == 0) ? 0 : (13 + (z - 1) * 12);  // 0,13,25,37
    const int L    = (z == 0) ? 13 : 12;
    const int t    = threadIdx.x;
    const int wid  = t >> 5;
    const int lane = t & 31;

    __shared__ int      sbinoff4[BINS];  // (h0*FW + w0) * NCH/4, float4 offset
    __shared__ unsigned smask[BINS];     // 4x4 validity bitmask (spans <= 4 here)
    __shared__ int      bofs4;           // batch offset in float4 units
    __shared__ __align__(16) float so[CG * LMAX];   // [c_local][bin_local], stride 13

    if (t < BINS) {
        // Boundary math matches XLA-CPU fast-math reference bit-for-bit:
        // exact IEEE ops EXCEPT division lowered as x * rn(1/7).
        const float R7 = 1.0f / 7.0f;
        float x1 = floorf(__fadd_rn(__fmul_rn(rois[n * 4 + 0], SCALE), 0.5f));
        float y1 = floorf(__fadd_rn(__fmul_rn(rois[n * 4 + 1], SCALE), 0.5f));
        float x2 = floorf(__fadd_rn(__fmul_rn(rois[n * 4 + 2], SCALE), 0.5f));
        float y2 = floorf(__fadd_rn(__fmul_rn(rois[n * 4 + 3], SCALE), 0.5f));
        float roi_w = fmaxf(__fadd_rn(__fsub_rn(x2, x1), 1.0f), 1.0f);
        float roi_h = fmaxf(__fadd_rn(__fsub_rn(y2, y1), 1.0f), 1.0f);
        float bin_h = __fmul_rn(roi_h, R7);
        float bin_w = __fmul_rn(roi_w, R7);

        int ph = t / PW;
        int pw = t - ph * PW;
        float fph = (float)ph, fpw = (float)pw;

        int h0 = (int)fminf(fmaxf(__fadd_rn(floorf(__fmul_rn(fph, bin_h)), y1), 0.0f), (float)FH);
        int h1 = (int)fminf(fmaxf(__fadd_rn(ceilf(__fmul_rn(__fadd_rn(fph, 1.0f), bin_h)), y1), 0.0f), (float)FH);
        int w0 = (int)fminf(fmaxf(__fadd_rn(floorf(__fmul_rn(fpw, bin_w)), x1), 0.0f), (float)FW);
        int w1 = (int)fminf(fmaxf(__fadd_rn(ceilf(__fmul_rn(__fadd_rn(fpw, 1.0f), bin_w)), x1), 0.0f), (float)FW);

        unsigned mh = 0, mw = 0;
#pragma unroll
        for (int d = 0; d < 4; ++d) {
            mh |= (h0 + d < h1) ? (1u << d) : 0u;
            mw |= (w0 + d < w1) ? (1u << d) : 0u;
        }
        unsigned mask = 0;
#pragma unroll
        for (int d = 0; d < 4; ++d)
            mask |= ((mh >> d) & 1u) ? (mw << (4 * d)) : 0u;

        sbinoff4[t] = (h0 * FW + w0) * (NCH / 4);
        smask[t]    = mask;
        if (t == 0) bofs4 = roib[n] * (HW * NCH / 4);
    }
    __syncthreads();

    // lane covers 4 consecutive channels via float4. Each warp handles only
    // 1-2 bins of this block's range -> short latency chains, high MLP.
    const float4* __restrict__ fb = g_feat_t4 + bofs4 + (c0 >> 2) + lane;

    for (int bl = wid; bl < L; bl += 8) {
        const int bin = b0 + bl;
        const unsigned mask = smask[bin];
        const float4* __restrict__ f = fb + sbinoff4[bin];
        float4 m = make_float4(-INFINITY, -INFINITY, -INFINITY, -INFINITY);
#pragma unroll
        for (int dh = 0; dh < 4; ++dh) {
#pragma unroll
            for (int dw = 0; dw < 4; ++dw) {
                if (mask & (1u << (dh * 4 + dw))) {
                    float4 v = f[(dh * FW + dw) * (NCH / 4)];
                    m.x = fmaxf(m.x, v.x);
                    m.y = fmaxf(m.y, v.y);
                    m.z = fmaxf(m.z, v.z);
                    m.w = fmaxf(m.w, v.w);
                }
            }
        }
        if (mask == 0u) m = make_float4(0.f, 0.f, 0.f, 0.f);  // empty bin -> 0
        const int cb = lane * 4;
        so[(cb + 0) * LMAX + bl] = m.x;
        so[(cb + 1) * LMAX + bl] = m.y;
        so[(cb + 2) * LMAX + bl] = m.z;
        so[(cb + 3) * LMAX + bl] = m.w;
    }
    __syncthreads();

    // Flush: per-channel contiguous runs of L floats into strided out region.
    float* __restrict__ op = out + n * TOTAL + c0 * BINS + b0;
    for (int e = t; e < CG * L; e += 256) {
        int c  = e / L;
        int bl = e - c * L;
        op[c * BINS + bl] = so[c * LMAX + bl];
    }
}

extern "C" void kernel_launch(void* const* d_in, const int* in_sizes, int n_in,
                              void* d_out, int out_size)
{
    const float* feat = (const float*)d_in[0];
    const float* rois = (const float*)d_in[1];
    const int*   rb   = (const int*)d_in[2];
    float*       out  = (float*)d_out;

    dim3 tg((HW + 31) / 32, NCH / 32, NB);   // (46, 8, 4)
    dim3 tb(32, 8);
    transpose_kernel<<<tg, tb>>>(feat);

    dim3 grid(NCGRP, 256, BS);               // (2, 256, 4) = 2048 CTAs
    roipool2_kernel<<<grid, 256>>>(rois, rb, out);
}

// round 16
// speedup vs baseline: 1.3489x; 1.3489x over previous
#include <cuda_runtime.h>
#include <math.h>

#define NB    4
#define NCH   256
#define FH    38
#define FW    38
#define HW    (FH * FW)            // 1444
#define PH    7
#define PW    7
#define SCALE 0.0625f
#define BINS  (PH * PW)            // 49
#define TOTAL (NCH * BINS)         // 12544
#define CG    128                  // channels per block (lane covers 4 via float4)
#define NCGRP (NCH / CG)           // 2
#define NT    512                  // threads per block (16 warps)

// Scratch: feat transposed to (B, H*W, C). float4 => 16B-aligned base.
__device__ float4 g_feat_t4[NB * HW * NCH / 4];

__global__ __launch_bounds__(256) void transpose_kernel(const float* __restrict__ feat)
{
    __shared__ float tile[32][33];
    const int b   = blockIdx.z;
    const int hw0 = blockIdx.x * 32;
    const int c0  = blockIdx.y * 32;
    const int tx  = threadIdx.x;     // 0..31
    const int ty  = threadIdx.y;     // 0..7

    const float* src = feat + b * NCH * HW;
#pragma unroll
    for (int i = 0; i < 4; ++i) {
        int c  = c0 + ty + i * 8;
        int hw = hw0 + tx;
        tile[ty + i * 8][tx] = (hw < HW) ? src[c * HW + hw] : 0.0f;
    }
    __syncthreads();
    float* dst = (float*)g_feat_t4 + b * HW * NCH;
#pragma unroll
    for (int i = 0; i < 4; ++i) {
        int hw = hw0 + ty + i * 8;
        int c  = c0 + tx;
        if (hw < HW) dst[hw * NCH + c] = tile[tx][ty + i * 8];
    }
}

__global__ __launch_bounds__(NT) void roipool2_kernel(
    const float* __restrict__ rois,
    const int*   __restrict__ roib,
    float*       __restrict__ out)
{
    const int n    = blockIdx.y;
    const int c0   = blockIdx.x * CG;
    const int t    = threadIdx.x;
    const int wid  = t >> 5;           // 0..15
    const int lane = t & 31;

    __shared__ int      sbinoff4[BINS];  // (h0*FW + w0) * NCH/4, float4 offset
    __shared__ unsigned smask[BINS];     // 4x4 validity bitmask (spans <= 4 here)
    __shared__ int      bofs4;           // batch offset in float4 units
    __shared__ __align__(16) float so[CG * BINS];   // [c_local][bin]

    if (t < BINS) {
        // Boundary math matches XLA-CPU fast-math reference bit-for-bit:
        // exact IEEE ops EXCEPT division lowered as x * rn(1/7).
        const float R7 = 1.0f / 7.0f;
        float x1 = floorf(__fadd_rn(__fmul_rn(rois[n * 4 + 0], SCALE), 0.5f));
        float y1 = floorf(__fadd_rn(__fmul_rn(rois[n * 4 + 1], SCALE), 0.5f));
        float x2 = floorf(__fadd_rn(__fmul_rn(rois[n * 4 + 2], SCALE), 0.5f));
        float y2 = floorf(__fadd_rn(__fmul_rn(rois[n * 4 + 3], SCALE), 0.5f));
        float roi_w = fmaxf(__fadd_rn(__fsub_rn(x2, x1), 1.0f), 1.0f);
        float roi_h = fmaxf(__fadd_rn(__fsub_rn(y2, y1), 1.0f), 1.0f);
        float bin_h = __fmul_rn(roi_h, R7);
        float bin_w = __fmul_rn(roi_w, R7);

        int ph = t / PW;
        int pw = t - ph * PW;
        float fph = (float)ph, fpw = (float)pw;

        int h0 = (int)fminf(fmaxf(__fadd_rn(floorf(__fmul_rn(fph, bin_h)), y1), 0.0f), (float)FH);
        int h1 = (int)fminf(fmaxf(__fadd_rn(ceilf(__fmul_rn(__fadd_rn(fph, 1.0f), bin_h)), y1), 0.0f), (float)FH);
        int w0 = (int)fminf(fmaxf(__fadd_rn(floorf(__fmul_rn(fpw, bin_w)), x1), 0.0f), (float)FW);
        int w1 = (int)fminf(fmaxf(__fadd_rn(ceilf(__fmul_rn(__fadd_rn(fpw, 1.0f), bin_w)), x1), 0.0f), (float)FW);

        unsigned mh = 0, mw = 0;
#pragma unroll
        for (int d = 0; d < 4; ++d) {
            mh |= (h0 + d < h1) ? (1u << d) : 0u;
            mw |= (w0 + d < w1) ? (1u << d) : 0u;
        }
        unsigned mask = 0;
#pragma unroll
        for (int d = 0; d < 4; ++d)
            mask |= ((mh >> d) & 1u) ? (mw << (4 * d)) : 0u;

        sbinoff4[t] = (h0 * FW + w0) * (NCH / 4);
        smask[t]    = mask;
        if (t == 0) bofs4 = roib[n] * (HW * NCH / 4);
    }
    __syncthreads();

    // lane covers 4 consecutive channels via float4. 16 warps split the 49
    // bins (3-4 each) -> short latency chains, doubled in-flight warps vs
    // the 256-thread version, same per-block fixed overhead.
    const float4* __restrict__ fb = g_feat_t4 + bofs4 + (c0 >> 2) + lane;

    for (int bin = wid; bin < BINS; bin += 16) {
        const unsigned mask = smask[bin];
        const float4* __restrict__ f = fb + sbinoff4[bin];
        float4 m = make_float4(-INFINITY, -INFINITY, -INFINITY, -INFINITY);
#pragma unroll
        for (int dh = 0; dh < 4; ++dh) {
#pragma unroll
            for (int dw = 0; dw < 4; ++dw) {
                if (mask & (1u << (dh * 4 + dw))) {
                    float4 v = f[(dh * FW + dw) * (NCH / 4)];
                    m.x = fmaxf(m.x, v.x);
                    m.y = fmaxf(m.y, v.y);
                    m.z = fmaxf(m.z, v.z);
                    m.w = fmaxf(m.w, v.w);
                }
            }
        }
        if (mask == 0u) m = make_float4(0.f, 0.f, 0.f, 0.f);  // empty bin -> 0
        const int cb = lane * 4;
        so[(cb + 0) * BINS + bin] = m.x;
        so[(cb + 1) * BINS + bin] = m.y;
        so[(cb + 2) * BINS + bin] = m.z;
        so[(cb + 3) * BINS + bin] = m.w;
    }
    __syncthreads();

    // Block's output region is contiguous: coalesced float4 flush, no divides.
    float4* __restrict__ op = (float4*)(out + n * TOTAL + c0 * BINS);
    const float4* __restrict__ sp = (const float4*)so;
#pragma unroll
    for (int e = t; e < CG * BINS / 4; e += NT)
        op[e] = sp[e];
}

extern "C" void kernel_launch(void* const* d_in, const int* in_sizes, int n_in,
                              void* d_out, int out_size)
{
    const float* feat = (const float*)d_in[0];
    const float* rois = (const float*)d_in[1];
    const int*   rb   = (const int*)d_in[2];
    float*       out  = (float*)d_out;

    dim3 tg((HW + 31) / 32, NCH / 32, NB);   // (46, 8, 4)
    dim3 tb(32, 8);
    transpose_kernel<<<tg, tb>>>(feat);

    dim3 grid(NCGRP, 256);                   // (2, 256), 512-thread blocks
    roipool2_kernel<<<grid, NT>>>(rois, rb, out);
}